// round 6
// baseline (speedup 1.0000x reference)
#include <cuda_runtime.h>

// AbstractRelu (DeepPoly ReLU relaxation), elementwise over N fp32.
// out layout: [relu(x) (N)] [lb_slope*low (N)] [relu(high) (N)]
//
// R6: fixed 2-quad unroll, SEQUENTIAL per-quad load->compute->store with a
// compiler memory fence between quads so q=1 loads are NOT front-batched
// (MLP_p1 stays 3; R2 showed front-batching 6 loads regresses via L1tex
// queue contention). Quad addresses are base and base+blockDim: each LDG.128
// remains fully coalesced. Halves CTA count vs R5 and overlaps q=0 stores
// with q=1 loads inside the thread.
// History: R1/R3 63.6us, R2 front-batch 65.6 (regr), R4 persistent 71.7
// (regr), R5 (128t) 63.3us = best.

__global__ void __launch_bounds__(128, 16)
abstract_relu_kernel(const float4* __restrict__ x,
                     const float4* __restrict__ low,
                     const float4* __restrict__ high,
                     float4* __restrict__ x_out,
                     float4* __restrict__ low_out,
                     float4* __restrict__ high_out,
                     int n4)
{
    // Block tile = 2 * blockDim quads; quad q for this thread at
    // tile_base + q*blockDim + tid  (each load instruction coalesced).
    const int tile_base = blockIdx.x * (blockDim.x * 2);
    int i = tile_base + threadIdx.x;

    #pragma unroll
    for (int q = 0; q < 2; q++) {
        if (i < n4) {
            float4 xv = __ldcs(&x[i]);
            float4 lv = __ldcs(&low[i]);
            float4 hv = __ldcs(&high[i]);

            float4 xo, lo, ho;

            #define LANE(f)                                                    \
            {                                                                  \
                float xe = xv.f, le = lv.f, he = hv.f;                         \
                xo.f = fmaxf(xe, 0.0f);                                        \
                ho.f = fmaxf(he, 0.0f);                                        \
                bool zero = (he <= 0.0f) || (le < 0.0f && le * le > he * he);  \
                lo.f = zero ? 0.0f : le;                                       \
            }

            LANE(x) LANE(y) LANE(z) LANE(w)
            #undef LANE

            __stcs(&x_out[i],    xo);
            __stcs(&low_out[i],  lo);
            __stcs(&high_out[i], ho);
        }
        // Prevent the compiler from hoisting quad 1's loads above quad 0's
        // stores (front-batching regressed in R2).
        asm volatile("" ::: "memory");
        i += blockDim.x;
    }
}

extern "C" void kernel_launch(void* const* d_in, const int* in_sizes, int n_in,
                              void* d_out, int out_size)
{
    const float* x    = (const float*)d_in[0];
    const float* low  = (const float*)d_in[1];
    const float* high = (const float*)d_in[2];
    float* out = (float*)d_out;

    const int n  = in_sizes[0];          // 16777216
    const int n4 = n / 4;                // 4194304

    float* x_out    = out;
    float* low_out  = out + n;
    float* high_out = out + 2 * (size_t)n;

    const int threads = 128;
    const int work    = threads * 2;
    const int blocks  = (n4 + work - 1) / work;   // 16384

    abstract_relu_kernel<<<blocks, threads>>>(
        (const float4*)x, (const float4*)low, (const float4*)high,
        (float4*)x_out, (float4*)low_out, (float4*)high_out, n4);
}